// round 14
// baseline (speedup 1.0000x reference)
#include <cuda_runtime.h>
#include <cuda_fp16.h>
#include <cstdint>
#include <cstddef>

// Problem constants
#define BB   32
#define HH   32
#define WW   32
#define CC   256
#define SS   (HH * WW)        // 1024
#define GG   32
#define CPG  (CC / GG)        // 8
#define MS   (BB * SS)        // 32768
#define EPS  1e-5f
#define ESHIFT 6.0f           // exp shift: u = exp(logit - ESHIFT)

// GEMM tile config (fp16 operands, fp32 accum) — proven geometry
#define BM 128
#define BN 128
#define BK 64
#define NSTAGE 3
#define RS 72                             // padded row stride in halves (144 B)
#define RSB2 272                          // TRANSB row stride in BYTES (136 halves)
#define A_SZH (BM * RS)
#define B_SZH (BN * RS)
#define STAGE_H (A_SZH + B_SZH)
#define SMEM_BYTES (NSTAGE * STAGE_H * 2) // 110592 bytes

// ---------------------------------------------------------------------------
// Scratch
// ---------------------------------------------------------------------------
__device__ __half g_ft  [(size_t)MS * CC];
__device__ __half g_qkv [(size_t)MS * 3 * CC];
__device__ __half g_p   [(size_t)BB * SS * SS];   // unnormalized exp(logits)
__device__ float  g_rsum[(size_t)MS];             // rowsum per (batch,query)
__device__ __half g_at  [(size_t)MS * CC];
__device__ __half g_wt  [4 * CC * CC];
__device__ float  g_bqkv[3 * CC];

// ---------------------------------------------------------------------------
// Helpers
// ---------------------------------------------------------------------------
__device__ __forceinline__ uint32_t smem_u32(const void* p) {
    uint32_t a;
    asm("{ .reg .u64 t; cvta.to.shared.u64 t, %1; cvt.u32.u64 %0, t; }" : "=r"(a) : "l"(p));
    return a;
}
__device__ __forceinline__ void cp16(uint32_t s, const void* g) {
    asm volatile("cp.async.cg.shared.global [%0], [%1], 16;" :: "r"(s), "l"(g));
}
__device__ __forceinline__ void ldmx4(uint32_t* r, uint32_t addr) {
    asm volatile("ldmatrix.sync.aligned.m8n8.x4.shared.b16 {%0,%1,%2,%3}, [%4];"
        : "=r"(r[0]), "=r"(r[1]), "=r"(r[2]), "=r"(r[3]) : "r"(addr));
}
__device__ __forceinline__ void ldmx4t(uint32_t* r, uint32_t addr) {
    asm volatile("ldmatrix.sync.aligned.m8n8.x4.trans.shared.b16 {%0,%1,%2,%3}, [%4];"
        : "=r"(r[0]), "=r"(r[1]), "=r"(r[2]), "=r"(r[3]) : "r"(addr));
}
__device__ __forceinline__ void mma_f16(float* d,
                                        uint32_t a0, uint32_t a1, uint32_t a2, uint32_t a3,
                                        uint32_t b0, uint32_t b1) {
    asm volatile(
        "mma.sync.aligned.m16n8k16.row.col.f32.f16.f16.f32 "
        "{%0,%1,%2,%3}, {%4,%5,%6,%7}, {%8,%9}, {%0,%1,%2,%3};"
        : "+f"(d[0]), "+f"(d[1]), "+f"(d[2]), "+f"(d[3])
        : "r"(a0), "r"(a1), "r"(a2), "r"(a3), "r"(b0), "r"(b1));
}

// ---------------------------------------------------------------------------
// GroupNorm -> fp16; blocks 0..31 also zero g_rsum (saves a launch)
// ---------------------------------------------------------------------------
__global__ void gn_kernel(const float* __restrict__ x,
                          const float* __restrict__ scale,
                          const float* __restrict__ bias)
{
    const int b = blockIdx.x / GG, g = blockIdx.x % GG, tid = threadIdx.x;

    if (blockIdx.x < 32) {
        float4* rz = (float4*)(g_rsum + (size_t)blockIdx.x * 1024);
        rz[tid] = make_float4(0.f, 0.f, 0.f, 0.f);
    }

    const float* xb = x + (size_t)b * SS * CC + g * CPG;

    float4 xv[4][2];
    float sum = 0.f, ssq = 0.f;
#pragma unroll
    for (int kk = 0; kk < 4; kk++) {
        const int s = tid + kk * 256;
        const float4* p = (const float4*)(xb + (size_t)s * CC);
        xv[kk][0] = p[0];
        xv[kk][1] = p[1];
        const float4 a = xv[kk][0], c = xv[kk][1];
        sum += a.x + a.y + a.z + a.w + c.x + c.y + c.z + c.w;
        ssq += a.x*a.x + a.y*a.y + a.z*a.z + a.w*a.w
             + c.x*c.x + c.y*c.y + c.z*c.z + c.w*c.w;
    }
    __shared__ float r0[256], r1[256];
    r0[tid] = sum; r1[tid] = ssq;
    __syncthreads();
    for (int off = 128; off > 0; off >>= 1) {
        if (tid < off) { r0[tid] += r0[tid + off]; r1[tid] += r1[tid + off]; }
        __syncthreads();
    }
    const float mean = r0[0] * (1.f / 8192.f);
    const float var  = r1[0] * (1.f / 8192.f) - mean * mean;
    const float inv  = rsqrtf(var + EPS);

    float sc[CPG], bi[CPG];
#pragma unroll
    for (int c = 0; c < CPG; c++) {
        sc[c] = scale[g * CPG + c] * inv;
        bi[c] = bias [g * CPG + c];
    }
    __half* fb = g_ft + (size_t)b * SS * CC + g * CPG;
#pragma unroll
    for (int kk = 0; kk < 4; kk++) {
        const int s = tid + kk * 256;
        __half2* fo = (__half2*)(fb + (size_t)s * CC);
        const float* xi = (const float*)&xv[kk][0];
#pragma unroll
        for (int c = 0; c < 4; c++) {
            const float v0 = (xi[2*c]   - mean) * sc[2*c]   + bi[2*c];
            const float v1 = (xi[2*c+1] - mean) * sc[2*c+1] + bi[2*c+1];
            fo[c] = __floats2half2_rn(v0, v1);
        }
    }
}

// ---------------------------------------------------------------------------
// Weight transpose -> fp16; block (0,0,0) also packs the QKV biases.
// ---------------------------------------------------------------------------
__global__ void transpose_w(const float* __restrict__ Wq, const float* __restrict__ Wk,
                            const float* __restrict__ Wv, const float* __restrict__ Wo,
                            const float* __restrict__ bq, const float* __restrict__ bk,
                            const float* __restrict__ bv)
{
    __shared__ float t[32][33];
    const int i = blockIdx.z;
    const float* W = (i == 0) ? Wq : (i == 1) ? Wk : (i == 2) ? Wv : Wo;
    const int kb = blockIdx.x * 32, nb = blockIdx.y * 32;
    const int tx = threadIdx.x, ty = threadIdx.y;
    const int tid = ty * 32 + tx;

    if (i == 0 && blockIdx.x == 0 && blockIdx.y == 0) {
        g_bqkv[tid]          = bq[tid];
        g_bqkv[tid + CC]     = bk[tid];
        g_bqkv[tid + 2 * CC] = bv[tid];
    }

#pragma unroll
    for (int j = 0; j < 4; j++)
        t[ty + j * 8][tx] = W[(size_t)(kb + ty + j * 8) * CC + nb + tx];
    __syncthreads();
    __half* out = g_wt + (size_t)i * CC * CC;
#pragma unroll
    for (int j = 0; j < 4; j++)
        out[(size_t)(nb + ty + j * 8) * CC + kb + tx] = __float2half_rn(t[tx][ty + j * 8]);
}

// ---------------------------------------------------------------------------
// fp16 tensor-core GEMM, fully compile-time specialized:
// KDIM, LDA, LDB, LDC, TRANSB, OUT_HALF, DO_EXP, SWAPXY all template params.
// CTA 128x128, warp 32x64, BK=64, 3-stage ring, ldmatrix.x4, 2 CTAs/SM.
// C[m,n] = alpha * sum_k A[m,k]*B[n,k] (+bias)(+resid)
// ---------------------------------------------------------------------------
template <int TRANSB, int KDIM, int LDA, int LDB, int LDC,
          int OUT_HALF, int DO_EXP, int SWAPXY>
__global__ void __launch_bounds__(256, 2)
mma_gemm(const __half* __restrict__ A, const __half* __restrict__ B,
         const float* __restrict__ bias, const float* __restrict__ resid,
         const float* __restrict__ rowinv, float* __restrict__ rsum_out,
         void* __restrict__ Cvoid,
         float alpha,
         long long sA, long long sB, long long sC)
{
    extern __shared__ __half sm[];
    const int batch = blockIdx.z;
    A += (size_t)batch * sA;
    B += (size_t)batch * sB;
    if (rowinv)   rowinv   += (size_t)batch * SS;
    if (rsum_out) rsum_out += (size_t)batch * SS;

    const int tid  = threadIdx.x;
    const int lane = tid & 31;
    const int wid  = tid >> 5;
    const int warp_m = wid & 3;
    const int warp_n = wid >> 2;
    const int bx = SWAPXY ? blockIdx.y : blockIdx.x;
    const int by = SWAPXY ? blockIdx.x : blockIdx.y;
    const int row0 = bx * BM;
    const int col0 = by * BN;

    const __half* Ab = A + (size_t)row0 * LDA;
    const __half* Bb = TRANSB ? (B + col0) : (B + (size_t)col0 * LDB);
    const uint32_t sbase = smem_u32(sm);

    const int ldr  = tid >> 3;
    const int ldcN = (tid & 7) * 8;

    auto load_stage = [&](int k0, int st) {
        const uint32_t abase = sbase + st * (STAGE_H * 2);
        const uint32_t bbase = abase + A_SZH * 2;
#pragma unroll
        for (int i = 0; i < 4; i++) {
            const int r = ldr + i * 32;
            cp16(abase + (r * RS + ldcN) * 2, Ab + (size_t)r * LDA + k0 + ldcN);
        }
        if (TRANSB) {
#pragma unroll
            for (int i = 0; i < 4; i++) {
                const int id = tid + i * 256;
                const int r  = id >> 4;            // key row 0..63
                const int ch = (id & 15) * 8;      // halves within row
                cp16(bbase + r * RSB2 + ch * 2, Bb + (size_t)(k0 + r) * LDB + ch);
            }
        } else {
#pragma unroll
            for (int i = 0; i < 4; i++) {
                const int r = ldr + i * 32;
                cp16(bbase + (r * RS + ldcN) * 2, Bb + (size_t)r * LDB + k0 + ldcN);
            }
        }
        asm volatile("cp.async.commit_group;" ::: "memory");
    };

    const int quad = lane >> 3;
    const int r8   = lane & 7;
    uint32_t a_off[2], b_off[4];
#pragma unroll
    for (int mt = 0; mt < 2; mt++) {
        const int row = warp_m * 32 + mt * 16 + (lane & 15);
        a_off[mt] = (row * RS + (lane >> 4) * 8) * 2;
    }
    if (TRANSB) {
#pragma unroll
        for (int ntp = 0; ntp < 4; ntp++) {
            const int kk = (quad & 1) * 8 + r8;                        // key row
            const int nn = warp_n * 64 + ntp * 16 + (quad >> 1) * 8;   // d col
            b_off[ntp] = A_SZH * 2 + kk * RSB2 + nn * 2;
        }
    } else {
#pragma unroll
        for (int ntp = 0; ntp < 4; ntp++) {
            const int n = warp_n * 64 + ntp * 16 + (quad >> 1) * 8 + r8;
            b_off[ntp] = A_SZH * 2 + (n * RS + (quad & 1) * 8) * 2;
        }
    }
    constexpr uint32_t koffB = TRANSB ? (16 * RSB2) : 32;

    float acc[2][8][4];
#pragma unroll
    for (int a = 0; a < 2; a++)
#pragma unroll
        for (int b = 0; b < 8; b++)
#pragma unroll
            for (int c = 0; c < 4; c++) acc[a][b][c] = 0.f;

    constexpr int NK = KDIM / BK;
    load_stage(0, 0);
    if (NK > 1) load_stage(BK, 1);

#pragma unroll
    for (int t = 0; t < NK; t++) {
        if (t + 1 < NK) asm volatile("cp.async.wait_group 1;" ::: "memory");
        else            asm volatile("cp.async.wait_group 0;" ::: "memory");
        __syncthreads();

        if (t + 2 < NK)
            load_stage((t + 2) * BK, (t + 2) % NSTAGE);

        const uint32_t stbase = sbase + (t % NSTAGE) * (STAGE_H * 2);

#pragma unroll
        for (int ks = 0; ks < 4; ks++) {
            const uint32_t koff = ks * 32;
            uint32_t a[2][4];
#pragma unroll
            for (int mt = 0; mt < 2; mt++)
                ldmx4(a[mt], stbase + a_off[mt] + koff);
            uint32_t b[8][2];
#pragma unroll
            for (int ntp = 0; ntp < 4; ntp++) {
                uint32_t tr[4];
                if (TRANSB) ldmx4t(tr, stbase + b_off[ntp] + ks * koffB);
                else        ldmx4 (tr, stbase + b_off[ntp] + ks * koffB);
                b[2*ntp][0]   = tr[0]; b[2*ntp][1]   = tr[1];
                b[2*ntp+1][0] = tr[2]; b[2*ntp+1][1] = tr[3];
            }
#pragma unroll
            for (int mt = 0; mt < 2; mt++)
#pragma unroll
                for (int nt = 0; nt < 8; nt++)
                    mma_f16(acc[mt][nt], a[mt][0], a[mt][1], a[mt][2], a[mt][3],
                            b[nt][0], b[nt][1]);
        }
    }

    // Epilogue
    const int g  = lane >> 2;
    const int tg = lane & 3;
    if (OUT_HALF) {
        __half* C = (__half*)Cvoid + (size_t)batch * sC;
#pragma unroll
        for (int mt = 0; mt < 2; mt++)
#pragma unroll
            for (int hf = 0; hf < 2; hf++) {
                const int r = row0 + warp_m * 32 + mt * 16 + hf * 8 + g;
                __half* Crow = C + (size_t)r * LDC;
                const float rs = rowinv ? (1.f / rowinv[r]) : 1.f;
                float rowpart = 0.f;
#pragma unroll
                for (int nt = 0; nt < 8; nt++) {
                    const int cix = col0 + warp_n * 64 + nt * 8 + tg * 2;
                    float v0 = acc[mt][nt][hf * 2 + 0] * alpha;
                    float v1 = acc[mt][nt][hf * 2 + 1] * alpha;
                    if (bias) { v0 += bias[cix]; v1 += bias[cix + 1]; }
                    if (DO_EXP) {
                        v0 = __expf(v0 - ESHIFT); v1 = __expf(v1 - ESHIFT);
                        rowpart += v0 + v1;
                    }
                    v0 *= rs; v1 *= rs;
                    *(__half2*)&Crow[cix] = __floats2half2_rn(v0, v1);
                }
                if (DO_EXP) {
                    rowpart += __shfl_xor_sync(0xFFFFFFFF, rowpart, 1);
                    rowpart += __shfl_xor_sync(0xFFFFFFFF, rowpart, 2);
                    if (tg == 0 && rsum_out) atomicAdd(&rsum_out[r], rowpart);
                }
            }
    } else {
        float* C = (float*)Cvoid + (size_t)batch * sC;
        const float* R = resid ? resid + (size_t)batch * sC : nullptr;
#pragma unroll
        for (int mt = 0; mt < 2; mt++)
#pragma unroll
            for (int hf = 0; hf < 2; hf++) {
                const int r = row0 + warp_m * 32 + mt * 16 + hf * 8 + g;
                float* Crow = C + (size_t)r * LDC;
                const float* Rrow = R ? R + (size_t)r * LDC : nullptr;
#pragma unroll
                for (int nt = 0; nt < 8; nt++) {
                    const int cix = col0 + warp_n * 64 + nt * 8 + tg * 2;
                    float v0 = acc[mt][nt][hf * 2 + 0] * alpha;
                    float v1 = acc[mt][nt][hf * 2 + 1] * alpha;
                    if (bias) { v0 += bias[cix]; v1 += bias[cix + 1]; }
                    if (Rrow) { v0 += Rrow[cix]; v1 += Rrow[cix + 1]; }
                    *(float2*)&Crow[cix] = make_float2(v0, v1);
                }
            }
    }
}

// Instantiation aliases: <TRANSB, KDIM, LDA, LDB, LDC, OUT_HALF, DO_EXP, SWAPXY>
#define GEMM_QKV    mma_gemm<0, 256, 256, 256, 768, 1, 0, 1>
#define GEMM_LOGITS mma_gemm<0, 256, 768, 768, 1024, 1, 1, 0>
#define GEMM_PV     mma_gemm<1, 1024, 1024, 768, 256, 1, 0, 0>
#define GEMM_OUT    mma_gemm<0, 256, 256, 256, 256, 0, 0, 1>

// ---------------------------------------------------------------------------
// Launch
// ---------------------------------------------------------------------------
extern "C" void kernel_launch(void* const* d_in, const int* in_sizes, int n_in,
                              void* d_out, int out_size)
{
    const float* x   = (const float*)d_in[0];
    const float* gsc = (const float*)d_in[1];
    const float* gbi = (const float*)d_in[2];
    const float* Wq  = (const float*)d_in[3];
    const float* bq  = (const float*)d_in[4];
    const float* Wk  = (const float*)d_in[5];
    const float* bk  = (const float*)d_in[6];
    const float* Wv  = (const float*)d_in[7];
    const float* bv  = (const float*)d_in[8];
    const float* Wo  = (const float*)d_in[9];
    const float* bo  = (const float*)d_in[10];
    float* out = (float*)d_out;

    cudaFuncSetAttribute((const void*)GEMM_QKV,
                         cudaFuncAttributeMaxDynamicSharedMemorySize, SMEM_BYTES);
    cudaFuncSetAttribute((const void*)GEMM_LOGITS,
                         cudaFuncAttributeMaxDynamicSharedMemorySize, SMEM_BYTES);
    cudaFuncSetAttribute((const void*)GEMM_PV,
                         cudaFuncAttributeMaxDynamicSharedMemorySize, SMEM_BYTES);
    cudaFuncSetAttribute((const void*)GEMM_OUT,
                         cudaFuncAttributeMaxDynamicSharedMemorySize, SMEM_BYTES);

    __half *ft, *qkv, *pb, *at, *wt;
    float *bqkv, *rsum;
    cudaGetSymbolAddress((void**)&ft,   g_ft);
    cudaGetSymbolAddress((void**)&qkv,  g_qkv);
    cudaGetSymbolAddress((void**)&pb,   g_p);
    cudaGetSymbolAddress((void**)&at,   g_at);
    cudaGetSymbolAddress((void**)&wt,   g_wt);
    cudaGetSymbolAddress((void**)&bqkv, g_bqkv);
    cudaGetSymbolAddress((void**)&rsum, g_rsum);

    const long long sQKV = (long long)SS * 3 * CC;
    const long long sBSS = (long long)SS * SS;
    const long long sBSC = (long long)SS * CC;

    // 1) GroupNorm (+rsum zero), weight transpose (+bias pack)
    gn_kernel<<<BB * GG, 256>>>(x, gsc, gbi);
    transpose_w<<<dim3(8, 8, 4), dim3(32, 8)>>>(Wq, Wk, Wv, Wo, bq, bk, bv);

    // 2) fused QKV projection -> half
    GEMM_QKV<<<dim3((3 * CC) / BN, MS / BM, 1), 256, SMEM_BYTES>>>(
        ft, wt, bqkv, nullptr, nullptr, nullptr, qkv, 1.f, 0, 0, 0);

    // 3) u = exp(QK^T/16 - ESHIFT) per batch -> half; row sums accumulated
    GEMM_LOGITS<<<dim3(SS / BM, SS / BN, BB), 256, SMEM_BYTES>>>(
        qkv + 0, qkv + CC, nullptr, nullptr, nullptr, rsum, pb,
        0.0625f, sQKV, sQKV, sBSS);

    // 4) attn = (u V) / S per batch -> half; V in [key][d] layout (TRANSB)
    GEMM_PV<<<dim3(SS / BM, CC / BN, BB), 256, SMEM_BYTES>>>(
        pb, qkv + 2 * CC, nullptr, nullptr, rsum, nullptr, at,
        1.f, sBSS, sQKV, sBSC);

    // 5) out = attn Wo + bo + x -> f32
    GEMM_OUT<<<dim3(CC / BN, MS / BM, 1), 256, SMEM_BYTES>>>(
        at, wt + 3 * CC * CC, bo, x, nullptr, nullptr, out, 1.f, 0, 0, 0);
}

// round 15
// speedup vs baseline: 1.0656x; 1.0656x over previous
#include <cuda_runtime.h>
#include <cuda_fp16.h>
#include <cstdint>
#include <cstddef>

// Problem constants
#define BB   32
#define HB   16               // batches per stream-half
#define HH   32
#define WW   32
#define CC   256
#define SS   (HH * WW)        // 1024
#define GG   32
#define CPG  (CC / GG)        // 8
#define MS   (BB * SS)        // 32768
#define EPS  1e-5f
#define ESHIFT 6.0f           // exp shift: u = exp(logit - ESHIFT)

// GEMM tile config (fp16 operands, fp32 accum) — R13 proven geometry
#define BM 128
#define BN 128
#define BK 64
#define NSTAGE 3
#define RS 72                             // padded row stride in halves (144 B)
#define RSB2 272                          // TRANSB row stride in BYTES (136 halves)
#define A_SZH (BM * RS)
#define B_SZH (BN * RS)
#define STAGE_H (A_SZH + B_SZH)
#define SMEM_BYTES (NSTAGE * STAGE_H * 2) // 110592 bytes

// ---------------------------------------------------------------------------
// Scratch
// ---------------------------------------------------------------------------
__device__ __half g_ft  [(size_t)MS * CC];
__device__ __half g_qkv [(size_t)MS * 3 * CC];
__device__ __half g_p   [(size_t)BB * SS * SS];   // unnormalized exp(logits)
__device__ float  g_rsum[(size_t)MS];             // rowsum per (batch,query)
__device__ __half g_at  [(size_t)MS * CC];
__device__ __half g_wt  [4 * CC * CC];
__device__ float  g_bqkv[3 * CC];

// ---------------------------------------------------------------------------
// Helpers
// ---------------------------------------------------------------------------
__device__ __forceinline__ uint32_t smem_u32(const void* p) {
    uint32_t a;
    asm("{ .reg .u64 t; cvta.to.shared.u64 t, %1; cvt.u32.u64 %0, t; }" : "=r"(a) : "l"(p));
    return a;
}
__device__ __forceinline__ void cp16(uint32_t s, const void* g) {
    asm volatile("cp.async.cg.shared.global [%0], [%1], 16;" :: "r"(s), "l"(g));
}
__device__ __forceinline__ void ldmx4(uint32_t* r, uint32_t addr) {
    asm volatile("ldmatrix.sync.aligned.m8n8.x4.shared.b16 {%0,%1,%2,%3}, [%4];"
        : "=r"(r[0]), "=r"(r[1]), "=r"(r[2]), "=r"(r[3]) : "r"(addr));
}
__device__ __forceinline__ void ldmx4t(uint32_t* r, uint32_t addr) {
    asm volatile("ldmatrix.sync.aligned.m8n8.x4.trans.shared.b16 {%0,%1,%2,%3}, [%4];"
        : "=r"(r[0]), "=r"(r[1]), "=r"(r[2]), "=r"(r[3]) : "r"(addr));
}
__device__ __forceinline__ void mma_f16(float* d,
                                        uint32_t a0, uint32_t a1, uint32_t a2, uint32_t a3,
                                        uint32_t b0, uint32_t b1) {
    asm volatile(
        "mma.sync.aligned.m16n8k16.row.col.f32.f16.f16.f32 "
        "{%0,%1,%2,%3}, {%4,%5,%6,%7}, {%8,%9}, {%0,%1,%2,%3};"
        : "+f"(d[0]), "+f"(d[1]), "+f"(d[2]), "+f"(d[3])
        : "r"(a0), "r"(a1), "r"(a2), "r"(a3), "r"(b0), "r"(b1));
}

// ---------------------------------------------------------------------------
// GroupNorm -> fp16; blocks 0..31 also zero g_rsum (saves a launch)
// ---------------------------------------------------------------------------
__global__ void gn_kernel(const float* __restrict__ x,
                          const float* __restrict__ scale,
                          const float* __restrict__ bias)
{
    const int b = blockIdx.x / GG, g = blockIdx.x % GG, tid = threadIdx.x;

    if (blockIdx.x < 32) {
        float4* rz = (float4*)(g_rsum + (size_t)blockIdx.x * 1024);
        rz[tid] = make_float4(0.f, 0.f, 0.f, 0.f);
    }

    const float* xb = x + (size_t)b * SS * CC + g * CPG;

    float4 xv[4][2];
    float sum = 0.f, ssq = 0.f;
#pragma unroll
    for (int kk = 0; kk < 4; kk++) {
        const int s = tid + kk * 256;
        const float4* p = (const float4*)(xb + (size_t)s * CC);
        xv[kk][0] = p[0];
        xv[kk][1] = p[1];
        const float4 a = xv[kk][0], c = xv[kk][1];
        sum += a.x + a.y + a.z + a.w + c.x + c.y + c.z + c.w;
        ssq += a.x*a.x + a.y*a.y + a.z*a.z + a.w*a.w
             + c.x*c.x + c.y*c.y + c.z*c.z + c.w*c.w;
    }
    __shared__ float r0[256], r1[256];
    r0[tid] = sum; r1[tid] = ssq;
    __syncthreads();
    for (int off = 128; off > 0; off >>= 1) {
        if (tid < off) { r0[tid] += r0[tid + off]; r1[tid] += r1[tid + off]; }
        __syncthreads();
    }
    const float mean = r0[0] * (1.f / 8192.f);
    const float var  = r1[0] * (1.f / 8192.f) - mean * mean;
    const float inv  = rsqrtf(var + EPS);

    float sc[CPG], bi[CPG];
#pragma unroll
    for (int c = 0; c < CPG; c++) {
        sc[c] = scale[g * CPG + c] * inv;
        bi[c] = bias [g * CPG + c];
    }
    __half* fb = g_ft + (size_t)b * SS * CC + g * CPG;
#pragma unroll
    for (int kk = 0; kk < 4; kk++) {
        const int s = tid + kk * 256;
        __half2* fo = (__half2*)(fb + (size_t)s * CC);
        const float* xi = (const float*)&xv[kk][0];
#pragma unroll
        for (int c = 0; c < 4; c++) {
            const float v0 = (xi[2*c]   - mean) * sc[2*c]   + bi[2*c];
            const float v1 = (xi[2*c+1] - mean) * sc[2*c+1] + bi[2*c+1];
            fo[c] = __floats2half2_rn(v0, v1);
        }
    }
}

// ---------------------------------------------------------------------------
// Weight transpose -> fp16; block (0,0,0) also packs the QKV biases.
// ---------------------------------------------------------------------------
__global__ void transpose_w(const float* __restrict__ Wq, const float* __restrict__ Wk,
                            const float* __restrict__ Wv, const float* __restrict__ Wo,
                            const float* __restrict__ bq, const float* __restrict__ bk,
                            const float* __restrict__ bv)
{
    __shared__ float t[32][33];
    const int i = blockIdx.z;
    const float* W = (i == 0) ? Wq : (i == 1) ? Wk : (i == 2) ? Wv : Wo;
    const int kb = blockIdx.x * 32, nb = blockIdx.y * 32;
    const int tx = threadIdx.x, ty = threadIdx.y;
    const int tid = ty * 32 + tx;

    if (i == 0 && blockIdx.x == 0 && blockIdx.y == 0) {
        g_bqkv[tid]          = bq[tid];
        g_bqkv[tid + CC]     = bk[tid];
        g_bqkv[tid + 2 * CC] = bv[tid];
    }

#pragma unroll
    for (int j = 0; j < 4; j++)
        t[ty + j * 8][tx] = W[(size_t)(kb + ty + j * 8) * CC + nb + tx];
    __syncthreads();
    __half* out = g_wt + (size_t)i * CC * CC;
#pragma unroll
    for (int j = 0; j < 4; j++)
        out[(size_t)(nb + ty + j * 8) * CC + kb + tx] = __float2half_rn(t[tx][ty + j * 8]);
}

// ---------------------------------------------------------------------------
// fp16 tensor-core GEMM. CTA 128x128, warp 32x64, BK=64, 3-stage ring,
// ldmatrix.x4, 2 CTAs/SM.  K compile-time (R13 proven configuration).
// C[m,n] = alpha * sum_k A[m,k]*B[n,k] (+bias)(+resid)
// TRANSB: B stored [K,N] row-major; loaded via ldmatrix.trans.
// do_exp: out = exp(val - ESHIFT) (half) and accumulate row sums into rsum_out.
// rowinv: out *= 1/rowinv[batch*SS + r].
// ---------------------------------------------------------------------------
template <int TRANSB, int KDIM>
__global__ void __launch_bounds__(256, 2)
mma_gemm(const __half* __restrict__ A, const __half* __restrict__ B,
         const float* __restrict__ bias, const float* __restrict__ resid,
         const float* __restrict__ rowinv, float* __restrict__ rsum_out,
         void* __restrict__ Cvoid,
         int lda, int ldb, int ldc,
         float alpha, int out_half, int do_exp, int swapxy,
         long long sA, long long sB, long long sC)
{
    extern __shared__ __half sm[];
    const int batch = blockIdx.z;
    A += (size_t)batch * sA;
    B += (size_t)batch * sB;
    if (rowinv)   rowinv   += (size_t)batch * SS;
    if (rsum_out) rsum_out += (size_t)batch * SS;

    const int tid  = threadIdx.x;
    const int lane = tid & 31;
    const int wid  = tid >> 5;
    const int warp_m = wid & 3;
    const int warp_n = wid >> 2;
    const int bx = swapxy ? blockIdx.y : blockIdx.x;
    const int by = swapxy ? blockIdx.x : blockIdx.y;
    const int row0 = bx * BM;
    const int col0 = by * BN;

    const __half* Ab = A + (size_t)row0 * lda;
    const __half* Bb = TRANSB ? (B + col0) : (B + (size_t)col0 * ldb);
    const uint32_t sbase = smem_u32(sm);

    const int ldr  = tid >> 3;
    const int ldcN = (tid & 7) * 8;

    auto load_stage = [&](int k0, int st) {
        const uint32_t abase = sbase + st * (STAGE_H * 2);
        const uint32_t bbase = abase + A_SZH * 2;
#pragma unroll
        for (int i = 0; i < 4; i++) {
            const int r = ldr + i * 32;
            cp16(abase + (r * RS + ldcN) * 2, Ab + (size_t)r * lda + k0 + ldcN);
        }
        if (TRANSB) {
#pragma unroll
            for (int i = 0; i < 4; i++) {
                const int id = tid + i * 256;
                const int r  = id >> 4;            // key row 0..63
                const int ch = (id & 15) * 8;      // halves within row
                cp16(bbase + r * RSB2 + ch * 2, Bb + (size_t)(k0 + r) * ldb + ch);
            }
        } else {
#pragma unroll
            for (int i = 0; i < 4; i++) {
                const int r = ldr + i * 32;
                cp16(bbase + (r * RS + ldcN) * 2, Bb + (size_t)r * ldb + k0 + ldcN);
            }
        }
        asm volatile("cp.async.commit_group;" ::: "memory");
    };

    const int quad = lane >> 3;
    const int r8   = lane & 7;
    uint32_t a_off[2], b_off[4];
#pragma unroll
    for (int mt = 0; mt < 2; mt++) {
        const int row = warp_m * 32 + mt * 16 + (lane & 15);
        a_off[mt] = (row * RS + (lane >> 4) * 8) * 2;
    }
    if (TRANSB) {
#pragma unroll
        for (int ntp = 0; ntp < 4; ntp++) {
            const int kk = (quad & 1) * 8 + r8;                        // key row
            const int nn = warp_n * 64 + ntp * 16 + (quad >> 1) * 8;   // d col
            b_off[ntp] = A_SZH * 2 + kk * RSB2 + nn * 2;
        }
    } else {
#pragma unroll
        for (int ntp = 0; ntp < 4; ntp++) {
            const int n = warp_n * 64 + ntp * 16 + (quad >> 1) * 8 + r8;
            b_off[ntp] = A_SZH * 2 + (n * RS + (quad & 1) * 8) * 2;
        }
    }
    const uint32_t koffB = TRANSB ? (16 * RSB2) : 32;

    float acc[2][8][4];
#pragma unroll
    for (int a = 0; a < 2; a++)
#pragma unroll
        for (int b = 0; b < 8; b++)
#pragma unroll
            for (int c = 0; c < 4; c++) acc[a][b][c] = 0.f;

    constexpr int NK = KDIM / BK;
    load_stage(0, 0);
    if (NK > 1) load_stage(BK, 1);

#pragma unroll
    for (int t = 0; t < NK; t++) {
        constexpr int W1 = 1;
        if (t + 1 < NK) asm volatile("cp.async.wait_group %0;" :: "n"(W1) : "memory");
        else            asm volatile("cp.async.wait_group 0;" ::: "memory");
        __syncthreads();

        if (t + 2 < NK)
            load_stage((t + 2) * BK, (t + 2) % NSTAGE);

        const uint32_t stbase = sbase + (t % NSTAGE) * (STAGE_H * 2);

#pragma unroll
        for (int ks = 0; ks < 4; ks++) {
            const uint32_t koff = ks * 32;
            uint32_t a[2][4];
#pragma unroll
            for (int mt = 0; mt < 2; mt++)
                ldmx4(a[mt], stbase + a_off[mt] + koff);
            uint32_t b[8][2];
#pragma unroll
            for (int ntp = 0; ntp < 4; ntp++) {
                uint32_t tr[4];
                if (TRANSB) ldmx4t(tr, stbase + b_off[ntp] + ks * koffB);
                else        ldmx4 (tr, stbase + b_off[ntp] + ks * koffB);
                b[2*ntp][0]   = tr[0]; b[2*ntp][1]   = tr[1];
                b[2*ntp+1][0] = tr[2]; b[2*ntp+1][1] = tr[3];
            }
#pragma unroll
            for (int mt = 0; mt < 2; mt++)
#pragma unroll
                for (int nt = 0; nt < 8; nt++)
                    mma_f16(acc[mt][nt], a[mt][0], a[mt][1], a[mt][2], a[mt][3],
                            b[nt][0], b[nt][1]);
        }
    }

    // Epilogue
    const int g  = lane >> 2;
    const int tg = lane & 3;
    if (out_half) {
        __half* C = (__half*)Cvoid + (size_t)batch * sC;
#pragma unroll
        for (int mt = 0; mt < 2; mt++)
#pragma unroll
            for (int hf = 0; hf < 2; hf++) {
                const int r = row0 + warp_m * 32 + mt * 16 + hf * 8 + g;
                __half* Crow = C + (size_t)r * ldc;
                const float rs = rowinv ? (1.f / rowinv[r]) : 1.f;
                float rowpart = 0.f;
#pragma unroll
                for (int nt = 0; nt < 8; nt++) {
                    const int cix = col0 + warp_n * 64 + nt * 8 + tg * 2;
                    float v0 = acc[mt][nt][hf * 2 + 0] * alpha;
                    float v1 = acc[mt][nt][hf * 2 + 1] * alpha;
                    if (bias) { v0 += bias[cix]; v1 += bias[cix + 1]; }
                    if (do_exp) {
                        v0 = __expf(v0 - ESHIFT); v1 = __expf(v1 - ESHIFT);
                        rowpart += v0 + v1;
                    }
                    v0 *= rs; v1 *= rs;
                    *(__half2*)&Crow[cix] = __floats2half2_rn(v0, v1);
                }
                if (do_exp) {
                    rowpart += __shfl_xor_sync(0xFFFFFFFF, rowpart, 1);
                    rowpart += __shfl_xor_sync(0xFFFFFFFF, rowpart, 2);
                    if (tg == 0 && rsum_out) atomicAdd(&rsum_out[r], rowpart);
                }
            }
    } else {
        float* C = (float*)Cvoid + (size_t)batch * sC;
        const float* R = resid ? resid + (size_t)batch * sC : nullptr;
#pragma unroll
        for (int mt = 0; mt < 2; mt++)
#pragma unroll
            for (int hf = 0; hf < 2; hf++) {
                const int r = row0 + warp_m * 32 + mt * 16 + hf * 8 + g;
                float* Crow = C + (size_t)r * ldc;
                const float* Rrow = R ? R + (size_t)r * ldc : nullptr;
#pragma unroll
                for (int nt = 0; nt < 8; nt++) {
                    const int cix = col0 + warp_n * 64 + nt * 8 + tg * 2;
                    float v0 = acc[mt][nt][hf * 2 + 0] * alpha;
                    float v1 = acc[mt][nt][hf * 2 + 1] * alpha;
                    if (bias) { v0 += bias[cix]; v1 += bias[cix + 1]; }
                    if (Rrow) { v0 += Rrow[cix]; v1 += Rrow[cix + 1]; }
                    *(float2*)&Crow[cix] = make_float2(v0, v1);
                }
            }
    }
}

// ---------------------------------------------------------------------------
// Launch: fork-join two batch-halves on side streams (capturable pattern)
// ---------------------------------------------------------------------------
extern "C" void kernel_launch(void* const* d_in, const int* in_sizes, int n_in,
                              void* d_out, int out_size)
{
    const float* x   = (const float*)d_in[0];
    const float* gsc = (const float*)d_in[1];
    const float* gbi = (const float*)d_in[2];
    const float* Wq  = (const float*)d_in[3];
    const float* bq  = (const float*)d_in[4];
    const float* Wk  = (const float*)d_in[5];
    const float* bk  = (const float*)d_in[6];
    const float* Wv  = (const float*)d_in[7];
    const float* bv  = (const float*)d_in[8];
    const float* Wo  = (const float*)d_in[9];
    const float* bo  = (const float*)d_in[10];
    float* out = (float*)d_out;

    static bool inited = false;
    static cudaStream_t w1, w2;
    static cudaEvent_t evS, evT, evQ, ev1, ev2;
    if (!inited) {
        cudaStreamCreateWithFlags(&w1, cudaStreamNonBlocking);
        cudaStreamCreateWithFlags(&w2, cudaStreamNonBlocking);
        cudaEventCreateWithFlags(&evS, cudaEventDisableTiming);
        cudaEventCreateWithFlags(&evT, cudaEventDisableTiming);
        cudaEventCreateWithFlags(&evQ, cudaEventDisableTiming);
        cudaEventCreateWithFlags(&ev1, cudaEventDisableTiming);
        cudaEventCreateWithFlags(&ev2, cudaEventDisableTiming);
        cudaFuncSetAttribute((const void*)mma_gemm<0, 256>,
                             cudaFuncAttributeMaxDynamicSharedMemorySize, SMEM_BYTES);
        cudaFuncSetAttribute((const void*)mma_gemm<1, 1024>,
                             cudaFuncAttributeMaxDynamicSharedMemorySize, SMEM_BYTES);
        inited = true;
    }

    __half *ft, *qkv, *pb, *at, *wt;
    float *bqkv, *rsum;
    cudaGetSymbolAddress((void**)&ft,   g_ft);
    cudaGetSymbolAddress((void**)&qkv,  g_qkv);
    cudaGetSymbolAddress((void**)&pb,   g_p);
    cudaGetSymbolAddress((void**)&at,   g_at);
    cudaGetSymbolAddress((void**)&wt,   g_wt);
    cudaGetSymbolAddress((void**)&bqkv, g_bqkv);
    cudaGetSymbolAddress((void**)&rsum, g_rsum);

    const long long sQKV = (long long)SS * 3 * CC;
    const long long sBSS = (long long)SS * SS;
    const long long sBSC = (long long)SS * CC;

    // Per-half element offsets
    const size_t oQKV = (size_t)HB * SS * 3 * CC;   // halves
    const size_t oP   = (size_t)HB * SS * SS;       // halves
    const size_t oAT  = (size_t)HB * SS * CC;       // halves
    const size_t oRS  = (size_t)HB * SS;            // floats
    const size_t oX   = (size_t)HB * SS * CC;       // floats

    // ---- fork marker on main (capture) stream ----
    cudaEventRecord(evS, 0);

    // Main stream: GroupNorm (+rsum zero)
    gn_kernel<<<BB * GG, 256>>>(x, gsc, gbi);

    // Side stream w1: weight transpose (+bias pack), concurrent with gn
    cudaStreamWaitEvent(w1, evS, 0);
    transpose_w<<<dim3(8, 8, 4), dim3(32, 8), 0, w1>>>(Wq, Wk, Wv, Wo, bq, bk, bv);
    cudaEventRecord(evT, w1);

    // QKV needs gn (main) + transpose_w (w1)
    cudaStreamWaitEvent(0, evT, 0);
    mma_gemm<0, 256><<<dim3((3 * CC) / BN, MS / BM, 1), 256, SMEM_BYTES>>>(
        ft, wt, bqkv, nullptr, nullptr, nullptr, qkv,
        CC, CC, 3 * CC, 1.f, 1, 0, 1, 0, 0, 0);
    cudaEventRecord(evQ, 0);

    // ---- half 1 (batches 0..15) on w1 ----
    cudaStreamWaitEvent(w1, evQ, 0);
    mma_gemm<0, 256><<<dim3(SS / BM, SS / BN, HB), 256, SMEM_BYTES, w1>>>(
        qkv + 0, qkv + CC, nullptr, nullptr, nullptr, rsum, pb,
        3 * CC, 3 * CC, SS, 0.0625f, 1, 1, 0, sQKV, sQKV, sBSS);
    mma_gemm<1, 1024><<<dim3(SS / BM, CC / BN, HB), 256, SMEM_BYTES, w1>>>(
        pb, qkv + 2 * CC, nullptr, nullptr, rsum, nullptr, at,
        SS, 3 * CC, CC, 1.f, 1, 0, 0, sBSS, sQKV, sBSC);
    mma_gemm<0, 256><<<dim3(CC / BN, (HB * SS) / BM, 1), 256, SMEM_BYTES, w1>>>(
        at, wt + 3 * CC * CC, bo, x, nullptr, nullptr, out,
        CC, CC, CC, 1.f, 0, 0, 1, 0, 0, 0);
    cudaEventRecord(ev1, w1);

    // ---- half 2 (batches 16..31) on w2 ----
    cudaStreamWaitEvent(w2, evQ, 0);
    mma_gemm<0, 256><<<dim3(SS / BM, SS / BN, HB), 256, SMEM_BYTES, w2>>>(
        qkv + oQKV, qkv + oQKV + CC, nullptr, nullptr, nullptr, rsum + oRS, pb + oP,
        3 * CC, 3 * CC, SS, 0.0625f, 1, 1, 0, sQKV, sQKV, sBSS);
    mma_gemm<1, 1024><<<dim3(SS / BM, CC / BN, HB), 256, SMEM_BYTES, w2>>>(
        pb + oP, qkv + oQKV + 2 * CC, nullptr, nullptr, rsum + oRS, nullptr, at + oAT,
        SS, 3 * CC, CC, 1.f, 1, 0, 0, sBSS, sQKV, sBSC);
    mma_gemm<0, 256><<<dim3(CC / BN, (HB * SS) / BM, 1), 256, SMEM_BYTES, w2>>>(
        at + oAT, wt + 3 * CC * CC, bo, x + oX, nullptr, nullptr, out + oX,
        CC, CC, CC, 1.f, 0, 0, 1, 0, 0, 0);
    cudaEventRecord(ev2, w2);

    // ---- join back to main stream ----
    cudaStreamWaitEvent(0, ev1, 0);
    cudaStreamWaitEvent(0, ev2, 0);
}

// round 16
// speedup vs baseline: 1.1049x; 1.0369x over previous
#include <cuda_runtime.h>
#include <cuda_fp16.h>
#include <cstdint>
#include <cstddef>

// Problem constants
#define BB   32
#define HB   16               // batches per stream-half
#define HH   32
#define WW   32
#define CC   256
#define SS   (HH * WW)        // 1024
#define GG   32
#define CPG  (CC / GG)        // 8
#define MS   (BB * SS)        // 32768
#define EPS  1e-5f
#define ESHIFT 6.0f           // exp shift: u = exp(logit - ESHIFT)

// GEMM tile config (fp16 operands, fp32 accum) — proven geometry
#define BM 128
#define BN 128
#define BK 64
#define NSTAGE 3
#define RS 72                             // padded row stride in halves (144 B)
#define RSB2 272                          // TRANSB row stride in BYTES (136 halves)
#define A_SZH (BM * RS)
#define B_SZH (BN * RS)
#define STAGE_H (A_SZH + B_SZH)
#define SMEM_BYTES (NSTAGE * STAGE_H * 2) // 110592 bytes

// ---------------------------------------------------------------------------
// Scratch
// ---------------------------------------------------------------------------
__device__ __half g_ft  [(size_t)MS * CC];
__device__ __half g_qkv [(size_t)MS * 3 * CC];
__device__ __half g_p   [(size_t)BB * SS * SS];   // unnormalized exp(logits)
__device__ float  g_rsum[(size_t)MS];             // rowsum per (batch,query)
__device__ __half g_at  [(size_t)MS * CC];
__device__ __half g_wt  [4 * CC * CC];
__device__ float  g_bqkv[3 * CC];

// ---------------------------------------------------------------------------
// Helpers
// ---------------------------------------------------------------------------
__device__ __forceinline__ uint32_t smem_u32(const void* p) {
    uint32_t a;
    asm("{ .reg .u64 t; cvta.to.shared.u64 t, %1; cvt.u32.u64 %0, t; }" : "=r"(a) : "l"(p));
    return a;
}
__device__ __forceinline__ void cp16(uint32_t s, const void* g) {
    asm volatile("cp.async.cg.shared.global [%0], [%1], 16;" :: "r"(s), "l"(g));
}
__device__ __forceinline__ void ldmx4(uint32_t* r, uint32_t addr) {
    asm volatile("ldmatrix.sync.aligned.m8n8.x4.shared.b16 {%0,%1,%2,%3}, [%4];"
        : "=r"(r[0]), "=r"(r[1]), "=r"(r[2]), "=r"(r[3]) : "r"(addr));
}
__device__ __forceinline__ void ldmx4t(uint32_t* r, uint32_t addr) {
    asm volatile("ldmatrix.sync.aligned.m8n8.x4.trans.shared.b16 {%0,%1,%2,%3}, [%4];"
        : "=r"(r[0]), "=r"(r[1]), "=r"(r[2]), "=r"(r[3]) : "r"(addr));
}
__device__ __forceinline__ void mma_f16(float* d,
                                        uint32_t a0, uint32_t a1, uint32_t a2, uint32_t a3,
                                        uint32_t b0, uint32_t b1) {
    asm volatile(
        "mma.sync.aligned.m16n8k16.row.col.f32.f16.f16.f32 "
        "{%0,%1,%2,%3}, {%4,%5,%6,%7}, {%8,%9}, {%0,%1,%2,%3};"
        : "+f"(d[0]), "+f"(d[1]), "+f"(d[2]), "+f"(d[3])
        : "r"(a0), "r"(a1), "r"(a2), "r"(a3), "r"(b0), "r"(b1));
}

// ---------------------------------------------------------------------------
// GroupNorm -> fp16 for batches [b0, b0+HB); blocks < HB zero this half's rsum
// ---------------------------------------------------------------------------
__global__ void gn_kernel(const float* __restrict__ x,
                          const float* __restrict__ scale,
                          const float* __restrict__ bias,
                          int b0)
{
    const int b = b0 + blockIdx.x / GG, g = blockIdx.x % GG, tid = threadIdx.x;

    if (blockIdx.x < HB) {
        float4* rz = (float4*)(g_rsum + ((size_t)b0 + blockIdx.x) * 1024);
        rz[tid] = make_float4(0.f, 0.f, 0.f, 0.f);
    }

    const float* xb = x + (size_t)b * SS * CC + g * CPG;

    float4 xv[4][2];
    float sum = 0.f, ssq = 0.f;
#pragma unroll
    for (int kk = 0; kk < 4; kk++) {
        const int s = tid + kk * 256;
        const float4* p = (const float4*)(xb + (size_t)s * CC);
        xv[kk][0] = p[0];
        xv[kk][1] = p[1];
        const float4 a = xv[kk][0], c = xv[kk][1];
        sum += a.x + a.y + a.z + a.w + c.x + c.y + c.z + c.w;
        ssq += a.x*a.x + a.y*a.y + a.z*a.z + a.w*a.w
             + c.x*c.x + c.y*c.y + c.z*c.z + c.w*c.w;
    }
    __shared__ float r0[256], r1[256];
    r0[tid] = sum; r1[tid] = ssq;
    __syncthreads();
    for (int off = 128; off > 0; off >>= 1) {
        if (tid < off) { r0[tid] += r0[tid + off]; r1[tid] += r1[tid + off]; }
        __syncthreads();
    }
    const float mean = r0[0] * (1.f / 8192.f);
    const float var  = r1[0] * (1.f / 8192.f) - mean * mean;
    const float inv  = rsqrtf(var + EPS);

    float sc[CPG], bi[CPG];
#pragma unroll
    for (int c = 0; c < CPG; c++) {
        sc[c] = scale[g * CPG + c] * inv;
        bi[c] = bias [g * CPG + c];
    }
    __half* fb = g_ft + (size_t)b * SS * CC + g * CPG;
#pragma unroll
    for (int kk = 0; kk < 4; kk++) {
        const int s = tid + kk * 256;
        __half2* fo = (__half2*)(fb + (size_t)s * CC);
        const float* xi = (const float*)&xv[kk][0];
#pragma unroll
        for (int c = 0; c < 4; c++) {
            const float v0 = (xi[2*c]   - mean) * sc[2*c]   + bi[2*c];
            const float v1 = (xi[2*c+1] - mean) * sc[2*c+1] + bi[2*c+1];
            fo[c] = __floats2half2_rn(v0, v1);
        }
    }
}

// ---------------------------------------------------------------------------
// Weight transpose -> fp16; block (0,0,0) also packs the QKV biases.
// ---------------------------------------------------------------------------
__global__ void transpose_w(const float* __restrict__ Wq, const float* __restrict__ Wk,
                            const float* __restrict__ Wv, const float* __restrict__ Wo,
                            const float* __restrict__ bq, const float* __restrict__ bk,
                            const float* __restrict__ bv)
{
    __shared__ float t[32][33];
    const int i = blockIdx.z;
    const float* W = (i == 0) ? Wq : (i == 1) ? Wk : (i == 2) ? Wv : Wo;
    const int kb = blockIdx.x * 32, nb = blockIdx.y * 32;
    const int tx = threadIdx.x, ty = threadIdx.y;
    const int tid = ty * 32 + tx;

    if (i == 0 && blockIdx.x == 0 && blockIdx.y == 0) {
        g_bqkv[tid]          = bq[tid];
        g_bqkv[tid + CC]     = bk[tid];
        g_bqkv[tid + 2 * CC] = bv[tid];
    }

#pragma unroll
    for (int j = 0; j < 4; j++)
        t[ty + j * 8][tx] = W[(size_t)(kb + ty + j * 8) * CC + nb + tx];
    __syncthreads();
    __half* out = g_wt + (size_t)i * CC * CC;
#pragma unroll
    for (int j = 0; j < 4; j++)
        out[(size_t)(nb + ty + j * 8) * CC + kb + tx] = __float2half_rn(t[tx][ty + j * 8]);
}

// ---------------------------------------------------------------------------
// fp16 tensor-core GEMM. CTA 128x128, warp 32x64, BK=64, 3-stage ring,
// ldmatrix.x4, 2 CTAs/SM.  K compile-time.
// C[m,n] = alpha * sum_k A[m,k]*B[n,k] (+bias)(+resid)
// TRANSB: B stored [K,N] row-major; loaded via ldmatrix.trans.
// do_exp: out = exp(val - ESHIFT) (half) and accumulate row sums into rsum_out.
// rowinv: out *= 1/rowinv[batch*SS + r].
// ---------------------------------------------------------------------------
template <int TRANSB, int KDIM>
__global__ void __launch_bounds__(256, 2)
mma_gemm(const __half* __restrict__ A, const __half* __restrict__ B,
         const float* __restrict__ bias, const float* __restrict__ resid,
         const float* __restrict__ rowinv, float* __restrict__ rsum_out,
         void* __restrict__ Cvoid,
         int lda, int ldb, int ldc,
         float alpha, int out_half, int do_exp, int swapxy,
         long long sA, long long sB, long long sC)
{
    extern __shared__ __half sm[];
    const int batch = blockIdx.z;
    A += (size_t)batch * sA;
    B += (size_t)batch * sB;
    if (rowinv)   rowinv   += (size_t)batch * SS;
    if (rsum_out) rsum_out += (size_t)batch * SS;

    const int tid  = threadIdx.x;
    const int lane = tid & 31;
    const int wid  = tid >> 5;
    const int warp_m = wid & 3;
    const int warp_n = wid >> 2;
    const int bx = swapxy ? blockIdx.y : blockIdx.x;
    const int by = swapxy ? blockIdx.x : blockIdx.y;
    const int row0 = bx * BM;
    const int col0 = by * BN;

    const __half* Ab = A + (size_t)row0 * lda;
    const __half* Bb = TRANSB ? (B + col0) : (B + (size_t)col0 * ldb);
    const uint32_t sbase = smem_u32(sm);

    const int ldr  = tid >> 3;
    const int ldcN = (tid & 7) * 8;

    auto load_stage = [&](int k0, int st) {
        const uint32_t abase = sbase + st * (STAGE_H * 2);
        const uint32_t bbase = abase + A_SZH * 2;
#pragma unroll
        for (int i = 0; i < 4; i++) {
            const int r = ldr + i * 32;
            cp16(abase + (r * RS + ldcN) * 2, Ab + (size_t)r * lda + k0 + ldcN);
        }
        if (TRANSB) {
#pragma unroll
            for (int i = 0; i < 4; i++) {
                const int id = tid + i * 256;
                const int r  = id >> 4;            // key row 0..63
                const int ch = (id & 15) * 8;      // halves within row
                cp16(bbase + r * RSB2 + ch * 2, Bb + (size_t)(k0 + r) * ldb + ch);
            }
        } else {
#pragma unroll
            for (int i = 0; i < 4; i++) {
                const int r = ldr + i * 32;
                cp16(bbase + (r * RS + ldcN) * 2, Bb + (size_t)r * ldb + k0 + ldcN);
            }
        }
        asm volatile("cp.async.commit_group;" ::: "memory");
    };

    const int quad = lane >> 3;
    const int r8   = lane & 7;
    uint32_t a_off[2], b_off[4];
#pragma unroll
    for (int mt = 0; mt < 2; mt++) {
        const int row = warp_m * 32 + mt * 16 + (lane & 15);
        a_off[mt] = (row * RS + (lane >> 4) * 8) * 2;
    }
    if (TRANSB) {
#pragma unroll
        for (int ntp = 0; ntp < 4; ntp++) {
            const int kk = (quad & 1) * 8 + r8;                        // key row
            const int nn = warp_n * 64 + ntp * 16 + (quad >> 1) * 8;   // d col
            b_off[ntp] = A_SZH * 2 + kk * RSB2 + nn * 2;
        }
    } else {
#pragma unroll
        for (int ntp = 0; ntp < 4; ntp++) {
            const int n = warp_n * 64 + ntp * 16 + (quad >> 1) * 8 + r8;
            b_off[ntp] = A_SZH * 2 + (n * RS + (quad & 1) * 8) * 2;
        }
    }
    const uint32_t koffB = TRANSB ? (16 * RSB2) : 32;

    float acc[2][8][4];
#pragma unroll
    for (int a = 0; a < 2; a++)
#pragma unroll
        for (int b = 0; b < 8; b++)
#pragma unroll
            for (int c = 0; c < 4; c++) acc[a][b][c] = 0.f;

    constexpr int NK = KDIM / BK;
    load_stage(0, 0);
    if (NK > 1) load_stage(BK, 1);

#pragma unroll
    for (int t = 0; t < NK; t++) {
        constexpr int W1 = 1;
        if (t + 1 < NK) asm volatile("cp.async.wait_group %0;" :: "n"(W1) : "memory");
        else            asm volatile("cp.async.wait_group 0;" ::: "memory");
        __syncthreads();

        if (t + 2 < NK)
            load_stage((t + 2) * BK, (t + 2) % NSTAGE);

        const uint32_t stbase = sbase + (t % NSTAGE) * (STAGE_H * 2);

#pragma unroll
        for (int ks = 0; ks < 4; ks++) {
            const uint32_t koff = ks * 32;
            uint32_t a[2][4];
#pragma unroll
            for (int mt = 0; mt < 2; mt++)
                ldmx4(a[mt], stbase + a_off[mt] + koff);
            uint32_t b[8][2];
#pragma unroll
            for (int ntp = 0; ntp < 4; ntp++) {
                uint32_t tr[4];
                if (TRANSB) ldmx4t(tr, stbase + b_off[ntp] + ks * koffB);
                else        ldmx4 (tr, stbase + b_off[ntp] + ks * koffB);
                b[2*ntp][0]   = tr[0]; b[2*ntp][1]   = tr[1];
                b[2*ntp+1][0] = tr[2]; b[2*ntp+1][1] = tr[3];
            }
#pragma unroll
            for (int mt = 0; mt < 2; mt++)
#pragma unroll
                for (int nt = 0; nt < 8; nt++)
                    mma_f16(acc[mt][nt], a[mt][0], a[mt][1], a[mt][2], a[mt][3],
                            b[nt][0], b[nt][1]);
        }
    }

    // Epilogue
    const int g  = lane >> 2;
    const int tg = lane & 3;
    if (out_half) {
        __half* C = (__half*)Cvoid + (size_t)batch * sC;
#pragma unroll
        for (int mt = 0; mt < 2; mt++)
#pragma unroll
            for (int hf = 0; hf < 2; hf++) {
                const int r = row0 + warp_m * 32 + mt * 16 + hf * 8 + g;
                __half* Crow = C + (size_t)r * ldc;
                const float rs = rowinv ? (1.f / rowinv[r]) : 1.f;
                float rowpart = 0.f;
#pragma unroll
                for (int nt = 0; nt < 8; nt++) {
                    const int cix = col0 + warp_n * 64 + nt * 8 + tg * 2;
                    float v0 = acc[mt][nt][hf * 2 + 0] * alpha;
                    float v1 = acc[mt][nt][hf * 2 + 1] * alpha;
                    if (bias) { v0 += bias[cix]; v1 += bias[cix + 1]; }
                    if (do_exp) {
                        v0 = __expf(v0 - ESHIFT); v1 = __expf(v1 - ESHIFT);
                        rowpart += v0 + v1;
                    }
                    v0 *= rs; v1 *= rs;
                    *(__half2*)&Crow[cix] = __floats2half2_rn(v0, v1);
                }
                if (do_exp) {
                    rowpart += __shfl_xor_sync(0xFFFFFFFF, rowpart, 1);
                    rowpart += __shfl_xor_sync(0xFFFFFFFF, rowpart, 2);
                    if (tg == 0 && rsum_out) atomicAdd(&rsum_out[r], rowpart);
                }
            }
    } else {
        float* C = (float*)Cvoid + (size_t)batch * sC;
        const float* R = resid ? resid + (size_t)batch * sC : nullptr;
#pragma unroll
        for (int mt = 0; mt < 2; mt++)
#pragma unroll
            for (int hf = 0; hf < 2; hf++) {
                const int r = row0 + warp_m * 32 + mt * 16 + hf * 8 + g;
                float* Crow = C + (size_t)r * ldc;
                const float* Rrow = R ? R + (size_t)r * ldc : nullptr;
#pragma unroll
                for (int nt = 0; nt < 8; nt++) {
                    const int cix = col0 + warp_n * 64 + nt * 8 + tg * 2;
                    float v0 = acc[mt][nt][hf * 2 + 0] * alpha;
                    float v1 = acc[mt][nt][hf * 2 + 1] * alpha;
                    if (bias) { v0 += bias[cix]; v1 += bias[cix + 1]; }
                    if (Rrow) { v0 += Rrow[cix]; v1 += Rrow[cix + 1]; }
                    *(float2*)&Crow[cix] = make_float2(v0, v1);
                }
            }
    }
}

// ---------------------------------------------------------------------------
// Launch: two fully independent per-half pipelines on side streams.
// ---------------------------------------------------------------------------
extern "C" void kernel_launch(void* const* d_in, const int* in_sizes, int n_in,
                              void* d_out, int out_size)
{
    const float* x   = (const float*)d_in[0];
    const float* gsc = (const float*)d_in[1];
    const float* gbi = (const float*)d_in[2];
    const float* Wq  = (const float*)d_in[3];
    const float* bq  = (const float*)d_in[4];
    const float* Wk  = (const float*)d_in[5];
    const float* bk  = (const float*)d_in[6];
    const float* Wv  = (const float*)d_in[7];
    const float* bv  = (const float*)d_in[8];
    const float* Wo  = (const float*)d_in[9];
    const float* bo  = (const float*)d_in[10];
    float* out = (float*)d_out;

    static bool inited = false;
    static cudaStream_t w1, w2;
    static cudaEvent_t evS, evT, ev1, ev2;
    if (!inited) {
        cudaStreamCreateWithFlags(&w1, cudaStreamNonBlocking);
        cudaStreamCreateWithFlags(&w2, cudaStreamNonBlocking);
        cudaEventCreateWithFlags(&evS, cudaEventDisableTiming);
        cudaEventCreateWithFlags(&evT, cudaEventDisableTiming);
        cudaEventCreateWithFlags(&ev1, cudaEventDisableTiming);
        cudaEventCreateWithFlags(&ev2, cudaEventDisableTiming);
        cudaFuncSetAttribute((const void*)mma_gemm<0, 256>,
                             cudaFuncAttributeMaxDynamicSharedMemorySize, SMEM_BYTES);
        cudaFuncSetAttribute((const void*)mma_gemm<1, 1024>,
                             cudaFuncAttributeMaxDynamicSharedMemorySize, SMEM_BYTES);
        inited = true;
    }

    __half *ft, *qkv, *pb, *at, *wt;
    float *bqkv, *rsum;
    cudaGetSymbolAddress((void**)&ft,   g_ft);
    cudaGetSymbolAddress((void**)&qkv,  g_qkv);
    cudaGetSymbolAddress((void**)&pb,   g_p);
    cudaGetSymbolAddress((void**)&at,   g_at);
    cudaGetSymbolAddress((void**)&wt,   g_wt);
    cudaGetSymbolAddress((void**)&bqkv, g_bqkv);
    cudaGetSymbolAddress((void**)&rsum, g_rsum);

    const long long sQKV = (long long)SS * 3 * CC;
    const long long sBSS = (long long)SS * SS;
    const long long sBSC = (long long)SS * CC;

    // Per-half element offsets
    const size_t oFT  = (size_t)HB * SS * CC;       // halves
    const size_t oQKV = (size_t)HB * SS * 3 * CC;   // halves
    const size_t oP   = (size_t)HB * SS * SS;       // halves
    const size_t oAT  = (size_t)HB * SS * CC;       // halves
    const size_t oRS  = (size_t)HB * SS;            // floats
    const size_t oX   = (size_t)HB * SS * CC;       // floats

    // ---- main stream: transpose_w (+bias pack), then fork ----
    transpose_w<<<dim3(8, 8, 4), dim3(32, 8)>>>(Wq, Wk, Wv, Wo, bq, bk, bv);
    cudaEventRecord(evT, 0);
    cudaEventRecord(evS, 0);

    // ---- half 1 pipeline on w1 (batches 0..15) ----
    cudaStreamWaitEvent(w1, evS, 0);
    gn_kernel<<<HB * GG, 256, 0, w1>>>(x, gsc, gbi, 0);
    mma_gemm<0, 256><<<dim3((3 * CC) / BN, (HB * SS) / BM, 1), 256, SMEM_BYTES, w1>>>(
        ft, wt, bqkv, nullptr, nullptr, nullptr, qkv,
        CC, CC, 3 * CC, 1.f, 1, 0, 1, 0, 0, 0);
    mma_gemm<0, 256><<<dim3(SS / BM, SS / BN, HB), 256, SMEM_BYTES, w1>>>(
        qkv + 0, qkv + CC, nullptr, nullptr, nullptr, rsum, pb,
        3 * CC, 3 * CC, SS, 0.0625f, 1, 1, 0, sQKV, sQKV, sBSS);
    mma_gemm<1, 1024><<<dim3(SS / BM, CC / BN, HB), 256, SMEM_BYTES, w1>>>(
        pb, qkv + 2 * CC, nullptr, nullptr, rsum, nullptr, at,
        SS, 3 * CC, CC, 1.f, 1, 0, 0, sBSS, sQKV, sBSC);
    mma_gemm<0, 256><<<dim3(CC / BN, (HB * SS) / BM, 1), 256, SMEM_BYTES, w1>>>(
        at, wt + 3 * CC * CC, bo, x, nullptr, nullptr, out,
        CC, CC, CC, 1.f, 0, 0, 1, 0, 0, 0);
    cudaEventRecord(ev1, w1);

    // ---- half 2 pipeline on w2 (batches 16..31) ----
    cudaStreamWaitEvent(w2, evS, 0);
    gn_kernel<<<HB * GG, 256, 0, w2>>>(x, gsc, gbi, HB);
    mma_gemm<0, 256><<<dim3((3 * CC) / BN, (HB * SS) / BM, 1), 256, SMEM_BYTES, w2>>>(
        ft + oFT, wt, bqkv, nullptr, nullptr, nullptr, qkv + oQKV,
        CC, CC, 3 * CC, 1.f, 1, 0, 1, 0, 0, 0);
    mma_gemm<0, 256><<<dim3(SS / BM, SS / BN, HB), 256, SMEM_BYTES, w2>>>(
        qkv + oQKV, qkv + oQKV + CC, nullptr, nullptr, nullptr, rsum + oRS, pb + oP,
        3 * CC, 3 * CC, SS, 0.0625f, 1, 1, 0, sQKV, sQKV, sBSS);
    mma_gemm<1, 1024><<<dim3(SS / BM, CC / BN, HB), 256, SMEM_BYTES, w2>>>(
        pb + oP, qkv + oQKV + 2 * CC, nullptr, nullptr, rsum + oRS, nullptr, at + oAT,
        SS, 3 * CC, CC, 1.f, 1, 0, 0, sBSS, sQKV, sBSC);
    mma_gemm<0, 256><<<dim3(CC / BN, (HB * SS) / BM, 1), 256, SMEM_BYTES, w2>>>(
        at + oAT, wt + 3 * CC * CC, bo, x + oX, nullptr, nullptr, out + oX,
        CC, CC, CC, 1.f, 0, 0, 1, 0, 0, 0);
    cudaEventRecord(ev2, w2);

    // NOTE: both QKV launches consume g_wt/g_bqkv — they must wait on evT.
    // evT was recorded on the main stream BEFORE the fork events were waited on,
    // and both streams' first dependency (evS) was recorded after evT on the
    // same main stream, so transpose_w is ordered before everything above.

    // ---- join back to main stream ----
    cudaStreamWaitEvent(0, ev1, 0);
    cudaStreamWaitEvent(0, ev2, 0);
}